// round 11
// baseline (speedup 1.0000x reference)
#include <cuda_runtime.h>
#include <cooperative_groups.h>
#include <math.h>
namespace cg = cooperative_groups;

#define NB 32
#define CD 512
#define PD 1600
#define KC 64
#define EPSF 1e-12f
#define TILE 32
#define NT 50
#define XP 34

// shared memory layout (float offsets)
#define OXT0 0            // x tile buf0 [512][34]
#define OXT1 17408        // x tile buf1
#define OWT  34816        // W^T [512][18]
#define OPS  44032        // score partials [16w][512]
#define OSC  52224        // scoreT / exp / soft [16][34]
#define OGM  52768        // per-pixel local max [32]
#define OGI  52800        // per-pixel weight factor [32]; [0] reused as global inv-norm
#define OPB  52832        // cluster exchange, 2 parity bufs of 64 floats
#define OBI  52960        // bias [16]
#define OMS  52976        // mass [16]
#define OSS  53000        // ss partials [64]; low 16 reused for row energies
#define OSK  53064        // per-k intra scale [16]
#define SMF  53080
#define SMB  (SMF * 4)

typedef unsigned long long ull;
__device__ __forceinline__ ull pk2(float v){ ull r; asm("mov.b64 %0,{%1,%1};":"=l"(r):"f"(v)); return r; }
__device__ __forceinline__ float2 up2(ull v){ float a,b; asm("mov.b64 {%0,%1},%2;":"=f"(a),"=f"(b):"l"(v)); return make_float2(a,b); }
__device__ __forceinline__ void fma2(ull&d, ull a, ull b){ asm("fma.rn.f32x2 %0,%1,%2,%0;":"+l"(d):"l"(a),"l"(b)); }
__device__ __forceinline__ void cpa8(unsigned dst, const float* src){
    asm volatile("cp.async.ca.shared.global [%0],[%1],8;"::"r"(dst),"l"(src));
}

// ---------------------------------------------------------------------------
// kmain: cluster of 4 CTAs per sample (rank kq = 16-cluster group), 512 thr.
// Per 32-px tile (x loaded once via cp.async double-buffer):
//   Phase A: 16 warp-private 32-channel slices -> score partials (2k x 8px
//            f32x2 per thread); smem reduce + bias -> scoreT.
//   Softmax: ONE cluster exchange of (local max, local expsum) pairs.
//   Phase B: agg[k][c] += soft*x from the SAME tile; thread 4k x 4c f32x2.
// Epilogue: mass, subtract mass*centroid, intra-norm, cluster-wide global
//           norm (DSMEM), single scaled store. No second kernel.
// ---------------------------------------------------------------------------
__global__ __launch_bounds__(512, 1) __cluster_dims__(4,1,1)
void kmain(const float* __restrict__ x, const float* __restrict__ conv_w,
           const float* __restrict__ conv_b, const float* __restrict__ cent,
           float* __restrict__ outp)
{
    extern __shared__ float sm[];
    cg::cluster_group cl = cg::this_cluster();
    const int t = threadIdx.x, w = t>>5, lane = t&31;
    const int kq = blockIdx.x, n = blockIdx.y, kbase = kq*16;
    const int kgA = lane>>2, pgA = lane&3;     // A: k-pair, pixel-octet
    const int kr = t>>5, pr = t&31;            // reduce/softmax: one (k,p) per thread
    const int kgB = (t>>7)<<2, cgB = t&127;    // B: k = kgB+i, c = cgB+128j
    const float* xb = x + (size_t)n*CD*PD;
    unsigned smb = (unsigned)__cvta_generic_to_shared(sm);

    // stage W^T [c][k] and bias (once)
#pragma unroll
    for (int i=0;i<16;i++)
        sm[OWT + t*18 + i] = conv_w[(size_t)(kbase+i)*CD + t];
    if (t < 16) sm[OBI+t] = conv_b[kbase+t];

    ull acc2[4][4];
#pragma unroll
    for (int i=0;i<4;i++)
#pragma unroll
        for (int j=0;j<4;j++) acc2[i][j]=0ULL;
    float msum = 0.f;

    // prologue: tile 0 -> buf0
#pragma unroll
    for (int i=0;i<16;i++){ int idx=t+512*i, r=idx>>4, o=(idx&15)*2;
        cpa8(smb + (unsigned)(OXT0 + r*XP + o)*4u, xb + (size_t)r*PD + o); }
    asm volatile("cp.async.commit_group;");

    for (int tile=0; tile<NT; tile++){
        float* cur = sm + ((tile&1)? OXT1:OXT0);
        if (tile+1 < NT){
            int bo = ((tile+1)&1)? OXT1:OXT0;
            int pn = (tile+1)*TILE;
#pragma unroll
            for (int i=0;i<16;i++){ int idx=t+512*i, r=idx>>4, o=(idx&15)*2;
                cpa8(smb + (unsigned)(bo + r*XP + o)*4u, xb + (size_t)r*PD + pn + o); }
            asm volatile("cp.async.commit_group;");
            asm volatile("cp.async.wait_group 1;");
        } else {
            asm volatile("cp.async.wait_group 0;");
        }
        __syncthreads();

        // ---- Phase A: warp-private 32-channel slice -> partials ----
        ull pa[2][4];
#pragma unroll
        for (int i=0;i<2;i++)
#pragma unroll
            for (int u=0;u<4;u++) pa[i][u]=0ULL;
        {
            const float* xw = cur + w*32*XP + pgA*8;
            const float* wp = sm + OWT + (w*32)*18 + kgA*2;
#pragma unroll 4
            for (int cc=0; cc<32; cc++){
                float2 wv = *(const float2*)wp;
                ull w0 = pk2(wv.x), w1 = pk2(wv.y);
#pragma unroll
                for (int u=0;u<4;u++){
                    ull xv = *(const ull*)(xw + 2*u);
                    fma2(pa[0][u], w0, xv);
                    fma2(pa[1][u], w1, xv);
                }
                xw += XP; wp += 18;
            }
        }
#pragma unroll
        for (int i=0;i<2;i++){
            int k = kgA*2 + i;
            int kc = (k & 14) + (kgA>>2);         // bank mix (2-way max)
#pragma unroll
            for (int u=0;u<4;u++){
                int pp = pgA*4 + u;
                int col = (pp + kc) & 15;
                *(float2*)(sm + OPS + w*512 + k*32 + col*2) = up2(pa[i][u]);
            }
        }
        __syncthreads();

        // ---- reduce 16 partials + bias -> scoreT ----
        float sc;
        {
            int colr = ((pr>>1) + (kr & 14) + (kr>>3)) & 15;
            const float* pb0 = sm + OPS + kr*32 + colr*2 + (pr&1);
            float s = 0.f;
#pragma unroll
            for (int wv=0; wv<16; wv++) s += pb0[wv*512];
            sc = s + sm[OBI + kr];
            sm[OSC + kr*34 + pr] = sc;
        }
        __syncthreads();

        // ---- softmax: single cluster exchange of (max, expsum) ----
        if (t < TILE){
            float m = -1e30f;
#pragma unroll
            for (int k=0;k<16;k++) m = fmaxf(m, sm[OSC + k*34 + t]);
            sm[OGM + t] = m;
        }
        __syncthreads();
        float e = __expf(sc - sm[OGM + pr]);
        sm[OSC + kr*34 + pr] = e;
        __syncthreads();
        {
            float2* pb = (float2*)(sm + OPB + (tile&1)*64);
            if (t < TILE){
                float s = 0.f;
#pragma unroll
                for (int k=0;k<16;k++) s += sm[OSC + k*34 + t];
                pb[t] = make_float2(sm[OGM + t], s);
            }
            cl.sync();
            if (t < TILE){
                float2 rv[4];
#pragma unroll
                for (int r=0;r<4;r++)
                    rv[r] = ((float2*)cl.map_shared_rank(pb, r))[t];
                float M = fmaxf(fmaxf(rv[0].x, rv[1].x), fmaxf(rv[2].x, rv[3].x));
                float S = rv[0].y*__expf(rv[0].x - M) + rv[1].y*__expf(rv[1].x - M)
                        + rv[2].y*__expf(rv[2].x - M) + rv[3].y*__expf(rv[3].x - M);
                sm[OGI + t] = __expf(sm[OGM + t] - M) / S;
            }
        }
        __syncthreads();
        {
            float wgt = e * sm[OGI + pr];
            sm[OSC + kr*34 + pr] = wgt;
            msum += wgt;
        }
        __syncthreads();

        // ---- Phase B: agg += soft * x (same tile) ----
        {
            const float* xc = cur + cgB*XP;
            const float* sp = sm + OSC + kgB*34;
#pragma unroll
            for (int pp=0; pp<16; pp++){
                ull sv[4], xv[4];
#pragma unroll
                for (int i=0;i<4;i++) sv[i] = *(const ull*)(sp + i*34 + 2*pp);
#pragma unroll
                for (int j=0;j<4;j++) xv[j] = *(const ull*)(xc + j*128*XP + 2*pp);
#pragma unroll
                for (int i=0;i<4;i++)
#pragma unroll
                    for (int j=0;j<4;j++) fma2(acc2[i][j], sv[i], xv[j]);
            }
        }
        __syncthreads();   // cur reused by cp.async next-next tile
    }

    // ---- epilogue ----
    // mass: warp w owns k=w (kr == w), 32 px lanes
#pragma unroll
    for (int o=1;o<32;o<<=1) msum += __shfl_xor_sync(0xffffffffu, msum, o);
    if (lane == 0) sm[OMS + w] = msum;
    __syncthreads();

    float v[4][4], ssk[4];
#pragma unroll
    for (int i=0;i<4;i++){
        float mass = sm[OMS + kgB + i];
        const float* cp = cent + (size_t)(kbase + kgB + i)*CD + cgB;
        ssk[i] = 0.f;
#pragma unroll
        for (int j=0;j<4;j++){
            float2 a = up2(acc2[i][j]);
            float val = a.x + a.y - mass*cp[j*128];
            v[i][j] = val; ssk[i] += val*val;
        }
    }
#pragma unroll
    for (int i=0;i<4;i++){
        float s = ssk[i];
#pragma unroll
        for (int o=1;o<32;o<<=1) s += __shfl_xor_sync(0xffffffffu, s, o);
        if (lane == 0) sm[OSS + w*4 + i] = s;
    }
    __syncthreads();
    if (t < 16){
        int g = t>>2, i = t&3;
        float s = sm[OSS + g*16 + i] + sm[OSS + g*16 + 4 + i]
                + sm[OSS + g*16 + 8 + i] + sm[OSS + g*16 + 12 + i];
        float denom = fmaxf(sqrtf(s), EPSF);
        sm[OSK + t] = 1.0f/denom;
        sm[OSS + t] = s/(denom*denom);       // post-norm row energy (1 or ~0)
    }
    __syncthreads();
    if (t == 0){
        float g16 = 0.f;
#pragma unroll
        for (int i=0;i<16;i++) g16 += sm[OSS + i];
        sm[OPB] = g16;                        // buf0: safe (last tile used buf1)
    }
    cl.sync();
    if (t == 0){
        float G = 0.f;
#pragma unroll
        for (int r=0;r<4;r++) G += *(const float*)cl.map_shared_rank(sm + OPB, r);
        sm[OGI] = 1.0f / fmaxf(sqrtf(G), EPSF);
    }
    __syncthreads();
    cl.sync();     // no rank exits while peers may still read its OPB
    const float ginv = sm[OGI];
#pragma unroll
    for (int i=0;i<4;i++){
        float scl = sm[OSK + kgB + i] * ginv;
        float* op = outp + ((size_t)n*KC + kbase + kgB + i)*CD + cgB;
#pragma unroll
        for (int j=0;j<4;j++) op[j*128] = v[i][j]*scl;
    }
}

// ---------------------------------------------------------------------------
extern "C" void kernel_launch(void* const* d_in, const int* in_sizes, int n_in,
                              void* d_out, int out_size)
{
    const float* x         = (const float*)d_in[0];
    const float* centroids = (const float*)d_in[1];
    const float* conv_w    = (const float*)d_in[2];
    const float* conv_b    = (const float*)d_in[3];
    float* out = (float*)d_out;

    cudaFuncSetAttribute(kmain, cudaFuncAttributeMaxDynamicSharedMemorySize, SMB);
    kmain<<<dim3(4, NB), 512, SMB>>>(x, conv_w, conv_b, centroids, out);
}

// round 12
// speedup vs baseline: 1.0001x; 1.0001x over previous
#include <cuda_runtime.h>
#include <cooperative_groups.h>
#include <math.h>
namespace cg = cooperative_groups;

#define NB 32
#define CD 512
#define PD 1600
#define KC 64
#define EPSF 1e-12f
#define TILE 32
#define NT 50
#define XP 34

// shared memory layout (float offsets)
#define OXT0 0            // x tile buf0 [512][34]
#define OXT1 17408        // x tile buf1
#define OWT  34816        // W^T [512][18]
#define OPS  44032        // score partials [16w][512]
#define OSC  52224        // scoreT / exp / soft [16][34]
#define OGM  52768        // per-pixel local max [32]
#define OGI  52800        // per-pixel weight factor [32]; [0] reused as global inv-norm
#define OPB  52832        // cluster exchange, 2 parity bufs of 64 floats
#define OBI  52960        // bias [16]
#define OMS  52976        // mass [16]
#define OSS  53000        // ss partials [64]; low 16 reused for row energies
#define OSK  53064        // per-k intra scale [16]
#define SMF  53080
#define SMB  (SMF * 4)

typedef unsigned long long ull;
__device__ __forceinline__ ull pk2(float v){ ull r; asm("mov.b64 %0,{%1,%1};":"=l"(r):"f"(v)); return r; }
__device__ __forceinline__ float2 up2(ull v){ float a,b; asm("mov.b64 {%0,%1},%2;":"=f"(a),"=f"(b):"l"(v)); return make_float2(a,b); }
__device__ __forceinline__ void fma2(ull&d, ull a, ull b){ asm("fma.rn.f32x2 %0,%1,%2,%0;":"+l"(d):"l"(a),"l"(b)); }
__device__ __forceinline__ void cpa8(unsigned dst, const float* src){
    asm volatile("cp.async.ca.shared.global [%0],[%1],8;"::"r"(dst),"l"(src));
}

// ---------------------------------------------------------------------------
// kmain: cluster of 4 CTAs per sample (rank kq = 16-cluster group), 512 thr.
// Per 32-px tile (x loaded once via cp.async double-buffer):
//   Phase A: 16 warp-private 32-channel slices -> score partials (2k x 8px
//            f32x2 per thread); smem reduce + bias -> scoreT.
//   Softmax: ONE cluster exchange of (local max, local expsum) pairs.
//   Phase B: agg[k][c] += soft*x from the SAME tile; thread 4k x 4c f32x2.
// Epilogue: mass, subtract mass*centroid, intra-norm, cluster-wide global
//           norm (DSMEM), single scaled store. No second kernel.
// ---------------------------------------------------------------------------
__global__ __launch_bounds__(512, 1) __cluster_dims__(4,1,1)
void kmain(const float* __restrict__ x, const float* __restrict__ conv_w,
           const float* __restrict__ conv_b, const float* __restrict__ cent,
           float* __restrict__ outp)
{
    extern __shared__ float sm[];
    cg::cluster_group cl = cg::this_cluster();
    const int t = threadIdx.x, w = t>>5, lane = t&31;
    const int kq = blockIdx.x, n = blockIdx.y, kbase = kq*16;
    const int kgA = lane>>2, pgA = lane&3;     // A: k-pair, pixel-octet
    const int kr = t>>5, pr = t&31;            // reduce/softmax: one (k,p) per thread
    const int kgB = (t>>7)<<2, cgB = t&127;    // B: k = kgB+i, c = cgB+128j
    const float* xb = x + (size_t)n*CD*PD;
    unsigned smb = (unsigned)__cvta_generic_to_shared(sm);

    // stage W^T [c][k] and bias (once)
#pragma unroll
    for (int i=0;i<16;i++)
        sm[OWT + t*18 + i] = conv_w[(size_t)(kbase+i)*CD + t];
    if (t < 16) sm[OBI+t] = conv_b[kbase+t];

    ull acc2[4][4];
#pragma unroll
    for (int i=0;i<4;i++)
#pragma unroll
        for (int j=0;j<4;j++) acc2[i][j]=0ULL;
    float msum = 0.f;

    // prologue: tile 0 -> buf0
#pragma unroll
    for (int i=0;i<16;i++){ int idx=t+512*i, r=idx>>4, o=(idx&15)*2;
        cpa8(smb + (unsigned)(OXT0 + r*XP + o)*4u, xb + (size_t)r*PD + o); }
    asm volatile("cp.async.commit_group;");

    for (int tile=0; tile<NT; tile++){
        float* cur = sm + ((tile&1)? OXT1:OXT0);
        if (tile+1 < NT){
            int bo = ((tile+1)&1)? OXT1:OXT0;
            int pn = (tile+1)*TILE;
#pragma unroll
            for (int i=0;i<16;i++){ int idx=t+512*i, r=idx>>4, o=(idx&15)*2;
                cpa8(smb + (unsigned)(bo + r*XP + o)*4u, xb + (size_t)r*PD + pn + o); }
            asm volatile("cp.async.commit_group;");
            asm volatile("cp.async.wait_group 1;");
        } else {
            asm volatile("cp.async.wait_group 0;");
        }
        __syncthreads();

        // ---- Phase A: warp-private 32-channel slice -> partials ----
        ull pa[2][4];
#pragma unroll
        for (int i=0;i<2;i++)
#pragma unroll
            for (int u=0;u<4;u++) pa[i][u]=0ULL;
        {
            const float* xw = cur + w*32*XP + pgA*8;
            const float* wp = sm + OWT + (w*32)*18 + kgA*2;
#pragma unroll 4
            for (int cc=0; cc<32; cc++){
                float2 wv = *(const float2*)wp;
                ull w0 = pk2(wv.x), w1 = pk2(wv.y);
#pragma unroll
                for (int u=0;u<4;u++){
                    ull xv = *(const ull*)(xw + 2*u);
                    fma2(pa[0][u], w0, xv);
                    fma2(pa[1][u], w1, xv);
                }
                xw += XP; wp += 18;
            }
        }
#pragma unroll
        for (int i=0;i<2;i++){
            int k = kgA*2 + i;
            int kc = (k & 14) + (kgA>>2);         // bank mix (2-way max)
#pragma unroll
            for (int u=0;u<4;u++){
                int pp = pgA*4 + u;
                int col = (pp + kc) & 15;
                *(float2*)(sm + OPS + w*512 + k*32 + col*2) = up2(pa[i][u]);
            }
        }
        __syncthreads();

        // ---- reduce 16 partials + bias -> scoreT ----
        float sc;
        {
            int colr = ((pr>>1) + (kr & 14) + (kr>>3)) & 15;
            const float* pb0 = sm + OPS + kr*32 + colr*2 + (pr&1);
            float s = 0.f;
#pragma unroll
            for (int wv=0; wv<16; wv++) s += pb0[wv*512];
            sc = s + sm[OBI + kr];
            sm[OSC + kr*34 + pr] = sc;
        }
        __syncthreads();

        // ---- softmax: single cluster exchange of (max, expsum) ----
        if (t < TILE){
            float m = -1e30f;
#pragma unroll
            for (int k=0;k<16;k++) m = fmaxf(m, sm[OSC + k*34 + t]);
            sm[OGM + t] = m;
        }
        __syncthreads();
        float e = __expf(sc - sm[OGM + pr]);
        sm[OSC + kr*34 + pr] = e;
        __syncthreads();
        {
            float2* pb = (float2*)(sm + OPB + (tile&1)*64);
            if (t < TILE){
                float s = 0.f;
#pragma unroll
                for (int k=0;k<16;k++) s += sm[OSC + k*34 + t];
                pb[t] = make_float2(sm[OGM + t], s);
            }
            cl.sync();
            if (t < TILE){
                float2 rv[4];
#pragma unroll
                for (int r=0;r<4;r++)
                    rv[r] = ((float2*)cl.map_shared_rank(pb, r))[t];
                float M = fmaxf(fmaxf(rv[0].x, rv[1].x), fmaxf(rv[2].x, rv[3].x));
                float S = rv[0].y*__expf(rv[0].x - M) + rv[1].y*__expf(rv[1].x - M)
                        + rv[2].y*__expf(rv[2].x - M) + rv[3].y*__expf(rv[3].x - M);
                sm[OGI + t] = __expf(sm[OGM + t] - M) / S;
            }
        }
        __syncthreads();
        {
            float wgt = e * sm[OGI + pr];
            sm[OSC + kr*34 + pr] = wgt;
            msum += wgt;
        }
        __syncthreads();

        // ---- Phase B: agg += soft * x (same tile) ----
        {
            const float* xc = cur + cgB*XP;
            const float* sp = sm + OSC + kgB*34;
#pragma unroll
            for (int pp=0; pp<16; pp++){
                ull sv[4], xv[4];
#pragma unroll
                for (int i=0;i<4;i++) sv[i] = *(const ull*)(sp + i*34 + 2*pp);
#pragma unroll
                for (int j=0;j<4;j++) xv[j] = *(const ull*)(xc + j*128*XP + 2*pp);
#pragma unroll
                for (int i=0;i<4;i++)
#pragma unroll
                    for (int j=0;j<4;j++) fma2(acc2[i][j], sv[i], xv[j]);
            }
        }
        __syncthreads();   // cur reused by cp.async next-next tile
    }

    // ---- epilogue ----
    // mass: warp w owns k=w (kr == w), 32 px lanes
#pragma unroll
    for (int o=1;o<32;o<<=1) msum += __shfl_xor_sync(0xffffffffu, msum, o);
    if (lane == 0) sm[OMS + w] = msum;
    __syncthreads();

    float v[4][4], ssk[4];
#pragma unroll
    for (int i=0;i<4;i++){
        float mass = sm[OMS + kgB + i];
        const float* cp = cent + (size_t)(kbase + kgB + i)*CD + cgB;
        ssk[i] = 0.f;
#pragma unroll
        for (int j=0;j<4;j++){
            float2 a = up2(acc2[i][j]);
            float val = a.x + a.y - mass*cp[j*128];
            v[i][j] = val; ssk[i] += val*val;
        }
    }
#pragma unroll
    for (int i=0;i<4;i++){
        float s = ssk[i];
#pragma unroll
        for (int o=1;o<32;o<<=1) s += __shfl_xor_sync(0xffffffffu, s, o);
        if (lane == 0) sm[OSS + w*4 + i] = s;
    }
    __syncthreads();
    if (t < 16){
        int g = t>>2, i = t&3;
        float s = sm[OSS + g*16 + i] + sm[OSS + g*16 + 4 + i]
                + sm[OSS + g*16 + 8 + i] + sm[OSS + g*16 + 12 + i];
        float denom = fmaxf(sqrtf(s), EPSF);
        sm[OSK + t] = 1.0f/denom;
        sm[OSS + t] = s/(denom*denom);       // post-norm row energy (1 or ~0)
    }
    __syncthreads();
    if (t == 0){
        float g16 = 0.f;
#pragma unroll
        for (int i=0;i<16;i++) g16 += sm[OSS + i];
        sm[OPB] = g16;                        // buf0: safe (last tile used buf1)
    }
    cl.sync();
    if (t == 0){
        float G = 0.f;
#pragma unroll
        for (int r=0;r<4;r++) G += *(const float*)cl.map_shared_rank(sm + OPB, r);
        sm[OGI] = 1.0f / fmaxf(sqrtf(G), EPSF);
    }
    __syncthreads();
    cl.sync();     // no rank exits while peers may still read its OPB
    const float ginv = sm[OGI];
#pragma unroll
    for (int i=0;i<4;i++){
        float scl = sm[OSK + kgB + i] * ginv;
        float* op = outp + ((size_t)n*KC + kbase + kgB + i)*CD + cgB;
#pragma unroll
        for (int j=0;j<4;j++) op[j*128] = v[i][j]*scl;
    }
}

// ---------------------------------------------------------------------------
extern "C" void kernel_launch(void* const* d_in, const int* in_sizes, int n_in,
                              void* d_out, int out_size)
{
    const float* x         = (const float*)d_in[0];
    const float* centroids = (const float*)d_in[1];
    const float* conv_w    = (const float*)d_in[2];
    const float* conv_b    = (const float*)d_in[3];
    float* out = (float*)d_out;

    cudaFuncSetAttribute(kmain, cudaFuncAttributeMaxDynamicSharedMemorySize, SMB);
    kmain<<<dim3(4, NB), 512, SMB>>>(x, conv_w, conv_b, centroids, out);
}